// round 12
// baseline (speedup 1.0000x reference)
#include <cuda_runtime.h>
#include <cuda_bf16.h>
#include <math.h>

// ============================================================================
// GAT: 2-layer graph attention, N=8192, F_in=29, F_hid=8, H=4, F_out=2
//
// exp-free O(N^2) inner loop:
//   w_ij = exp(LReLU(f1_i+f2_j) - C_i) = max(E1p_i*E2p_j, E1n_i*E2n_j)
// attn1 is SMEM-crossbar-bound (broadcast LDS.128 = 512B delivered):
// 4 rows/thread amortizes the per-j broadcast over 4 rows -> crossbar
// demand halves; fma pipe becomes the wall (~82us floor).
// ============================================================================

#define N_NODES   8192
#define F_IN      29
#define F_HID     8
#define N_HEADS   4
#define GAT_ALPHA 0.2f

#define NCH1      64                     // attn1 j-chunks (1 tile per CTA)
#define JCH1      (N_NODES / NCH1)       // 128
#define NCH2      16                     // attn2 j-chunks
#define JCH2      (N_NODES / NCH2)       // 512
#define TJ        128                    // attn1 SMEM tile of j's

typedef unsigned long long ull;

// ---------------------------------------------------------------------------
// f32x2 helpers
// ---------------------------------------------------------------------------
__device__ __forceinline__ ull f2mul(ull a, ull b) {
    ull r; asm("mul.rn.f32x2 %0, %1, %2;" : "=l"(r) : "l"(a), "l"(b)); return r;
}
__device__ __forceinline__ ull f2add(ull a, ull b) {
    ull r; asm("add.rn.f32x2 %0, %1, %2;" : "=l"(r) : "l"(a), "l"(b)); return r;
}
__device__ __forceinline__ ull f2fma(ull a, ull b, ull c) {
    ull r; asm("fma.rn.f32x2 %0, %1, %2, %3;" : "=l"(r) : "l"(a), "l"(b), "l"(c)); return r;
}
__device__ __forceinline__ float2 f2lohi(ull v) {
    float2 r; asm("mov.b64 {%0, %1}, %2;" : "=f"(r.x), "=f"(r.y) : "l"(v)); return r;
}
__device__ __forceinline__ ull f2pack(float x, float y) {
    ull r; asm("mov.b64 %0, {%1, %2};" : "=l"(r) : "f"(x), "f"(y)); return r;
}

// exact, order-independent float atomic max
__device__ __forceinline__ void atomicMaxF(float* addr, float v) {
    if (v >= 0.f) atomicMax((int*)addr, __float_as_int(v));
    else          atomicMin((unsigned int*)addr, __float_as_uint(v));
}

// ---------------------------------------------------------------------------
// Device scratch (static)
// ---------------------------------------------------------------------------
__device__ __align__(16) uint4 g_adjT4[(N_NODES / 128) * N_NODES];   // 8 MB [g128][i]
__device__ __align__(16) float g_tile1[N_NODES * 40];
__device__ __align__(16) float g_row1[N_NODES * 8];
__device__ float g_f1_1[N_NODES * N_HEADS];
__device__ float g_f2_1[N_NODES * N_HEADS];
__device__ float g_m2[8];
__device__ float g_part1[NCH1 * N_NODES * 36];          // 75.5 MB
__device__ __align__(16) float g_tile2F[4 * N_NODES];
__device__ float g_row2[N_NODES * 2];
__device__ float g_f1_2[N_NODES];
__device__ float g_f2_2[N_NODES];
__device__ float g_part2[NCH2 * N_NODES * 4];

// ---------------------------------------------------------------------------
// K0: pack adj into uint4 bitmasks (permuted bit order, transposed) + init m2
// ---------------------------------------------------------------------------
__global__ void gat_pack_adj(const int* __restrict__ adj) {
    if (blockIdx.x == 0 && threadIdx.x < 8)
        g_m2[threadIdx.x] = __int_as_float(0xff800000);
    int gw   = (blockIdx.x * blockDim.x + threadIdx.x) >> 5;
    int lane = threadIdx.x & 31;
    int i = gw & (N_NODES - 1);
    int g = gw >> 13;
    const int4* p = (const int4*)(adj + (size_t)i * N_NODES + g * 128);
    int4 v = p[lane];
    unsigned m0 = __ballot_sync(0xFFFFFFFFu, v.x > 0);
    unsigned m1 = __ballot_sync(0xFFFFFFFFu, v.y > 0);
    unsigned m2 = __ballot_sync(0xFFFFFFFFu, v.z > 0);
    unsigned m3 = __ballot_sync(0xFFFFFFFFu, v.w > 0);
    if (lane == 0) g_adjT4[g * N_NODES + i] = make_uint4(m0, m1, m2, m3);
}

// ---------------------------------------------------------------------------
// K1: h = x@W per head, f1/f2, fused per-head max(f2)
// ---------------------------------------------------------------------------
__global__ void gat_prep1(const float* __restrict__ x,
                          const float* __restrict__ Wh,
                          const float* __restrict__ ah) {
    __shared__ float sW[N_HEADS * F_IN * F_HID];
    __shared__ float sa[N_HEADS * 2 * F_HID];
    for (int q = threadIdx.x; q < N_HEADS * F_IN * F_HID; q += blockDim.x) sW[q] = Wh[q];
    if (threadIdx.x < 64) sa[threadIdx.x] = ah[threadIdx.x];
    __syncthreads();

    int i = blockIdx.x * blockDim.x + threadIdx.x;
    int lane = threadIdx.x & 31;
    float xr[F_IN];
#pragma unroll
    for (int c = 0; c < F_IN; c++) xr[c] = x[i * F_IN + c];

#pragma unroll
    for (int h = 0; h < N_HEADS; h++) {
        float hv[F_HID];
#pragma unroll
        for (int k = 0; k < F_HID; k++) hv[k] = 0.f;
#pragma unroll
        for (int c = 0; c < F_IN; c++) {
            float xc = xr[c];
#pragma unroll
            for (int k = 0; k < F_HID; k++)
                hv[k] = fmaf(xc, sW[h * (F_IN * F_HID) + c * F_HID + k], hv[k]);
        }
        float f1 = 0.f, f2 = 0.f;
#pragma unroll
        for (int k = 0; k < F_HID; k++) {
            f1 = fmaf(hv[k], sa[h * 16 + k], f1);
            f2 = fmaf(hv[k], sa[h * 16 + 8 + k], f2);
        }
        int gp = h >> 1, o = h & 1;
#pragma unroll
        for (int k = 0; k < F_HID; k++)
            g_tile1[i * 40 + 8 + gp * 16 + k * 2 + o] = hv[k];
        g_f1_1[i * N_HEADS + h] = f1;
        g_f2_1[i * N_HEADS + h] = f2;
        float m = f2;
#pragma unroll
        for (int s = 16; s > 0; s >>= 1) m = fmaxf(m, __shfl_xor_sync(0xFFFFFFFFu, m, s));
        if (lane == 0) atomicMaxF(&g_m2[h], m);
    }
}

// ---------------------------------------------------------------------------
// K2: layer-1 E1/E2 factors
// ---------------------------------------------------------------------------
__global__ void gat_prep1b() {
    int i = blockIdx.x * blockDim.x + threadIdx.x;
#pragma unroll
    for (int h = 0; h < N_HEADS; h++) {
        int gp = h >> 1, o = h & 1;
        float m2 = g_m2[h];
        float t  = g_f1_1[i * N_HEADS + h] + m2;
        float C  = fmaxf(t, GAT_ALPHA * t);
        g_row1[i * 8 + gp * 4 + o]     = expf(t - C);
        g_row1[i * 8 + gp * 4 + 2 + o] = expf(GAT_ALPHA * t - C);
        float u = g_f2_1[i * N_HEADS + h] - m2;
        g_tile1[i * 40 + gp * 4 + o]     = expf(u);
        g_tile1[i * 40 + gp * 4 + 2 + o] = expf(GAT_ALPHA * u);
    }
}

// ---------------------------------------------------------------------------
// K3: layer-1 attention. 128 threads: warps 0-1 = head-pair 0, warps 2-3 =
// head-pair 1. Each thread: 4 rows (i0, +64, +128, +192); CTA covers 256
// rows x one 128-j tile. Grid (32, 64) = 2048 CTAs, 2 CTAs/SM -> 7 waves
// at 99% utilization. 5 LDS.128 broadcasts amortized over 4 rows.
// ---------------------------------------------------------------------------
__global__ void __launch_bounds__(128, 2) gat_attn1() {
    __shared__ __align__(16) float tile[TJ * 40];   // 20 KB

    int t  = threadIdx.x & 63;
    int hp = threadIdx.x >> 6;        // 0 or 1
    int i0 = blockIdx.x * 256 + t;    // rows i0, i0+64, i0+128, i0+192
    int jbase = blockIdx.y * JCH1;

    ulonglong2 e0 = *(const ulonglong2*)(g_row1 + (size_t)i0 * 8 + hp * 4);
    ulonglong2 e1 = *(const ulonglong2*)(g_row1 + (size_t)(i0 + 64) * 8 + hp * 4);
    ulonglong2 e2 = *(const ulonglong2*)(g_row1 + (size_t)(i0 + 128) * 8 + hp * 4);
    ulonglong2 e3 = *(const ulonglong2*)(g_row1 + (size_t)(i0 + 192) * 8 + hp * 4);

    ull den0 = 0, den1 = 0, den2 = 0, den3 = 0;
    ull acc0[F_HID], acc1[F_HID], acc2[F_HID], acc3[F_HID];
#pragma unroll
    for (int k = 0; k < F_HID; k++) { acc0[k] = 0; acc1[k] = 0; acc2[k] = 0; acc3[k] = 0; }

    // single 128-j tile (JCH1 == TJ)
    {
        const float4* src = (const float4*)(g_tile1 + (size_t)jbase * 40);
        float4* dst = (float4*)tile;
#pragma unroll
        for (int q = 0; q < 10; q++) dst[threadIdx.x + q * 128] = src[threadIdx.x + q * 128];
        __syncthreads();

        int g = jbase >> 7;
        uint4 B0 = g_adjT4[(size_t)g * N_NODES + i0];
        uint4 B1 = g_adjT4[(size_t)g * N_NODES + i0 + 64];
        uint4 B2 = g_adjT4[(size_t)g * N_NODES + i0 + 128];
        uint4 B3 = g_adjT4[(size_t)g * N_NODES + i0 + 192];
        unsigned mw0[4] = {B0.x, B0.y, B0.z, B0.w};
        unsigned mw1[4] = {B1.x, B1.y, B1.z, B1.w};
        unsigned mw2[4] = {B2.x, B2.y, B2.z, B2.w};
        unsigned mw3[4] = {B3.x, B3.y, B3.z, B3.w};

        for (int c = 0; c < 4; c++) {
            unsigned m0 = mw0[c], m1 = mw1[c], m2 = mw2[c], m3 = mw3[c];
#pragma unroll 4
            for (int l = 0; l < 32; l++) {
                const float* tr = tile + (4 * l + c) * 40;
                ulonglong2 E2 = *(const ulonglong2*)(tr + hp * 4);   // E2p, E2n

                // per-row weights (fma: 8 MUL2; alu: max/sel)
                ull wa0, wa1, wa2, wa3;
                {
                    ull p = f2mul(e0.x, E2.x), n = f2mul(e0.y, E2.y);
                    float2 pp = f2lohi(p), nn = f2lohi(n);
                    bool a = (m0 >> l) & 1u;
                    wa0 = f2pack(a ? fmaxf(pp.x, nn.x) : 0.f, a ? fmaxf(pp.y, nn.y) : 0.f);
                }
                {
                    ull p = f2mul(e1.x, E2.x), n = f2mul(e1.y, E2.y);
                    float2 pp = f2lohi(p), nn = f2lohi(n);
                    bool a = (m1 >> l) & 1u;
                    wa1 = f2pack(a ? fmaxf(pp.x, nn.x) : 0.f, a ? fmaxf(pp.y, nn.y) : 0.f);
                }
                {
                    ull p = f2mul(e2.x, E2.x), n = f2mul(e2.y, E2.y);
                    float2 pp = f2lohi(p), nn = f2lohi(n);
                    bool a = (m2 >> l) & 1u;
                    wa2 = f2pack(a ? fmaxf(pp.x, nn.x) : 0.f, a ? fmaxf(pp.y, nn.y) : 0.f);
                }
                {
                    ull p = f2mul(e3.x, E2.x), n = f2mul(e3.y, E2.y);
                    float2 pp = f2lohi(p), nn = f2lohi(n);
                    bool a = (m3 >> l) & 1u;
                    wa3 = f2pack(a ? fmaxf(pp.x, nn.x) : 0.f, a ? fmaxf(pp.y, nn.y) : 0.f);
                }
                den0 = f2add(den0, wa0);
                den1 = f2add(den1, wa1);
                den2 = f2add(den2, wa2);
                den3 = f2add(den3, wa3);

                const ulonglong2* hb = (const ulonglong2*)(tr + 8 + hp * 16);
#pragma unroll
                for (int q = 0; q < 4; q++) {
                    ulonglong2 u = hb[q];
                    acc0[2 * q]     = f2fma(wa0, u.x, acc0[2 * q]);
                    acc0[2 * q + 1] = f2fma(wa0, u.y, acc0[2 * q + 1]);
                    acc1[2 * q]     = f2fma(wa1, u.x, acc1[2 * q]);
                    acc1[2 * q + 1] = f2fma(wa1, u.y, acc1[2 * q + 1]);
                    acc2[2 * q]     = f2fma(wa2, u.x, acc2[2 * q]);
                    acc2[2 * q + 1] = f2fma(wa2, u.y, acc2[2 * q + 1]);
                    acc3[2 * q]     = f2fma(wa3, u.x, acc3[2 * q]);
                    acc3[2 * q + 1] = f2fma(wa3, u.y, acc3[2 * q + 1]);
                }
            }
        }
    }

    // partials: heads 2hp (lo) and 2hp+1 (hi), rows i0..i0+192
    float* p0 = g_part1 + ((size_t)blockIdx.y * N_NODES + i0) * 36 + hp * 18;
    float* p1 = g_part1 + ((size_t)blockIdx.y * N_NODES + i0 + 64) * 36 + hp * 18;
    float* p2 = g_part1 + ((size_t)blockIdx.y * N_NODES + i0 + 128) * 36 + hp * 18;
    float* p3 = g_part1 + ((size_t)blockIdx.y * N_NODES + i0 + 192) * 36 + hp * 18;
#pragma unroll
    for (int k = 0; k < F_HID; k++) {
        float2 v;
        v = f2lohi(acc0[k]); p0[k] = v.x; p0[9 + k] = v.y;
        v = f2lohi(acc1[k]); p1[k] = v.x; p1[9 + k] = v.y;
        v = f2lohi(acc2[k]); p2[k] = v.x; p2[9 + k] = v.y;
        v = f2lohi(acc3[k]); p3[k] = v.x; p3[9 + k] = v.y;
    }
    {
        float2 v;
        v = f2lohi(den0); p0[8] = v.x; p0[17] = v.y;
        v = f2lohi(den1); p1[8] = v.x; p1[17] = v.y;
        v = f2lohi(den2); p2[8] = v.x; p2[17] = v.y;
        v = f2lohi(den3); p3[8] = v.x; p3[17] = v.y;
    }
}

// ---------------------------------------------------------------------------
// K4: combine layer-1 partials, ELU, layer-2 h/f1/f2, fused max(f2_2)
// ---------------------------------------------------------------------------
__global__ void gat_comb1(const float* __restrict__ Wout,
                          const float* __restrict__ aout) {
    int i = blockIdx.x * blockDim.x + threadIdx.x;
    int lane = threadIdx.x & 31;
    float den[N_HEADS];
    float acc[N_HEADS][F_HID];
#pragma unroll
    for (int h = 0; h < N_HEADS; h++) {
        den[h] = 0.f;
#pragma unroll
        for (int k = 0; k < F_HID; k++) acc[h][k] = 0.f;
    }
    for (int c = 0; c < NCH1; c++) {
        const float* p = g_part1 + ((size_t)c * N_NODES + i) * 36;
#pragma unroll
        for (int h = 0; h < N_HEADS; h++) {
#pragma unroll
            for (int k = 0; k < F_HID; k++) acc[h][k] += p[h * 9 + k];
            den[h] += p[h * 9 + 8];
        }
    }
    float hc[N_HEADS * F_HID];
#pragma unroll
    for (int h = 0; h < N_HEADS; h++) {
        float inv = 1.0f / den[h];
#pragma unroll
        for (int k = 0; k < F_HID; k++) {
            float o = acc[h][k] * inv;
            hc[h * 8 + k] = (o > 0.f) ? o : expm1f(o);
        }
    }
    float h2_0 = 0.f, h2_1 = 0.f;
#pragma unroll
    for (int q = 0; q < 32; q++) {
        h2_0 = fmaf(hc[q], __ldg(&Wout[q * 2 + 0]), h2_0);
        h2_1 = fmaf(hc[q], __ldg(&Wout[q * 2 + 1]), h2_1);
    }
    float a0 = __ldg(&aout[0]), a1 = __ldg(&aout[1]);
    float a2 = __ldg(&aout[2]), a3 = __ldg(&aout[3]);
    g_tile2F[2 * N_NODES + i] = h2_0;
    g_tile2F[3 * N_NODES + i] = h2_1;
    g_f1_2[i] = h2_0 * a0 + h2_1 * a1;
    float f2 = h2_0 * a2 + h2_1 * a3;
    g_f2_2[i] = f2;
    float m = f2;
#pragma unroll
    for (int s = 16; s > 0; s >>= 1) m = fmaxf(m, __shfl_xor_sync(0xFFFFFFFFu, m, s));
    if (lane == 0) atomicMaxF(&g_m2[4], m);
}

// ---------------------------------------------------------------------------
// K5: layer-2 E1/E2
// ---------------------------------------------------------------------------
__global__ void gat_prep2() {
    int i = blockIdx.x * blockDim.x + threadIdx.x;
    float m2 = g_m2[4];
    float t = g_f1_2[i] + m2;
    float C = fmaxf(t, GAT_ALPHA * t);
    g_row2[i * 2]     = expf(t - C);
    g_row2[i * 2 + 1] = expf(GAT_ALPHA * t - C);
    float u = g_f2_2[i] - m2;
    g_tile2F[0 * N_NODES + i] = expf(u);
    g_tile2F[1 * N_NODES + i] = expf(GAT_ALPHA * u);
}

// ---------------------------------------------------------------------------
// K6: layer-2 attention. 2 rows/thread, j-pairs packed, chunk 512 in SMEM.
// Grid (32, NCH2) = 512 CTAs of 128 threads.  (R9 config — proven.)
// ---------------------------------------------------------------------------
__global__ void __launch_bounds__(128, 6) gat_attn2() {
    __shared__ __align__(16) float tE[4][JCH2];   // 8 KB
    int t = threadIdx.x;
    int i0 = blockIdx.x * 256 + t;
    int i1 = i0 + 128;
    int jbase = blockIdx.y * JCH2;

#pragma unroll
    for (int f = 0; f < 4; f++) {
        const float4* src = (const float4*)(g_tile2F + (size_t)f * N_NODES + jbase);
        float4* dst = (float4*)tE[f];
        dst[t] = src[t];   // 512 floats = 128 float4 per field
    }
    __syncthreads();

    ull e1p0 = f2pack(g_row2[i0 * 2], g_row2[i0 * 2]);
    ull e1n0 = f2pack(g_row2[i0 * 2 + 1], g_row2[i0 * 2 + 1]);
    ull e1p1 = f2pack(g_row2[i1 * 2], g_row2[i1 * 2]);
    ull e1n1 = f2pack(g_row2[i1 * 2 + 1], g_row2[i1 * 2 + 1]);

    ull den0 = 0, a00 = 0, a10 = 0;
    ull den1 = 0, a01 = 0, a11 = 0;

    for (int jt = 0; jt < JCH2; jt += 128) {
        int g = (jbase + jt) >> 7;
        uint4 B0 = g_adjT4[(size_t)g * N_NODES + i0];
        uint4 B1 = g_adjT4[(size_t)g * N_NODES + i1];
        unsigned mw0[4] = {B0.x, B0.y, B0.z, B0.w};
        unsigned mw1[4] = {B1.x, B1.y, B1.z, B1.w};

#pragma unroll
        for (int cc = 0; cc < 4; cc += 2) {
            unsigned m0a = mw0[cc], m0b = mw0[cc + 1];
            unsigned m1a = mw1[cc], m1b = mw1[cc + 1];
#pragma unroll 8
            for (int l = 0; l < 32; l++) {
                int jloc = jt + 4 * l + cc;
                ull E2p2 = *(const ull*)(&tE[0][jloc]);
                ull E2n2 = *(const ull*)(&tE[1][jloc]);
                ull H02  = *(const ull*)(&tE[2][jloc]);
                ull H12  = *(const ull*)(&tE[3][jloc]);
                bool a0a = (m0a >> l) & 1u, a0b = (m0b >> l) & 1u;
                bool a1a = (m1a >> l) & 1u, a1b = (m1b >> l) & 1u;

                ull wp0 = f2mul(e1p0, E2p2), wn0 = f2mul(e1n0, E2n2);
                ull wp1 = f2mul(e1p1, E2p2), wn1 = f2mul(e1n1, E2n2);
                float2 p0 = f2lohi(wp0), n0 = f2lohi(wn0);
                float2 p1 = f2lohi(wp1), n1 = f2lohi(wn1);
                float w00 = a0a ? fmaxf(p0.x, n0.x) : 0.f;
                float w01 = a0b ? fmaxf(p0.y, n0.y) : 0.f;
                float w10 = a1a ? fmaxf(p1.x, n1.x) : 0.f;
                float w11 = a1b ? fmaxf(p1.y, n1.y) : 0.f;
                ull w0 = f2pack(w00, w01), w1 = f2pack(w10, w11);
                den0 = f2add(den0, w0);
                a00 = f2fma(w0, H02, a00);
                a10 = f2fma(w0, H12, a10);
                den1 = f2add(den1, w1);
                a01 = f2fma(w1, H02, a01);
                a11 = f2fma(w1, H12, a11);
            }
        }
    }

    {
        float2 d = f2lohi(den0), x0 = f2lohi(a00), x1 = f2lohi(a10);
        float* p = g_part2 + ((size_t)blockIdx.y * N_NODES + i0) * 4;
        p[0] = d.x + d.y; p[1] = x0.x + x0.y; p[2] = x1.x + x1.y;
    }
    {
        float2 d = f2lohi(den1), x0 = f2lohi(a01), x1 = f2lohi(a11);
        float* p = g_part2 + ((size_t)blockIdx.y * N_NODES + i1) * 4;
        p[0] = d.x + d.y; p[1] = x0.x + x0.y; p[2] = x1.x + x1.y;
    }
}

// ---------------------------------------------------------------------------
// K7: combine, ELU, log_softmax
// ---------------------------------------------------------------------------
__global__ void gat_final(float* __restrict__ out) {
    int i = blockIdx.x * blockDim.x + threadIdx.x;
    float den = 0.f, a0 = 0.f, a1 = 0.f;
    for (int c = 0; c < NCH2; c++) {
        const float* p = g_part2 + ((size_t)c * N_NODES + i) * 4;
        den += p[0]; a0 += p[1]; a1 += p[2];
    }
    float inv = 1.0f / den;
    float o0 = a0 * inv; o0 = (o0 > 0.f) ? o0 : expm1f(o0);
    float o1 = a1 * inv; o1 = (o1 > 0.f) ? o1 : expm1f(o1);
    float m = fmaxf(o0, o1);
    float l = logf(expf(o0 - m) + expf(o1 - m)) + m;
    out[i * 2]     = o0 - l;
    out[i * 2 + 1] = o1 - l;
}

// ---------------------------------------------------------------------------
// launch (attn1 is launch #4 for the ncu window)
// ---------------------------------------------------------------------------
extern "C" void kernel_launch(void* const* d_in, const int* in_sizes, int n_in,
                              void* d_out, int out_size) {
    const float* x  = nullptr;
    const int*   adj = nullptr;
    const float* Wh = nullptr;
    const float* ah = nullptr;
    const float* Wo = nullptr;
    const float* ao = nullptr;
    int found64 = 0;
    for (int k = 0; k < n_in; k++) {
        long s = in_sizes[k];
        if (s == (long)N_NODES * F_IN)          x   = (const float*)d_in[k];
        else if (s == (long)N_NODES * N_NODES)  adj = (const int*)d_in[k];
        else if (s == N_HEADS * F_IN * F_HID)   Wh  = (const float*)d_in[k];
        else if (s == 64) { if (found64++ == 0) ah = (const float*)d_in[k]; else Wo = (const float*)d_in[k]; }
        else if (s == 4)                        ao  = (const float*)d_in[k];
    }

    gat_pack_adj<<<65536, 256>>>(adj);
    gat_prep1<<<N_NODES / 128, 128>>>(x, Wh, ah);
    gat_prep1b<<<N_NODES / 128, 128>>>();
    gat_attn1<<<dim3(N_NODES / 256, NCH1), 128>>>();
    gat_comb1<<<N_NODES / 128, 128>>>(Wo, ao);
    gat_prep2<<<N_NODES / 128, 128>>>();
    gat_attn2<<<dim3(N_NODES / 256, NCH2), 128>>>();
    gat_final<<<N_NODES / 128, 128>>>((float*)d_out);
    (void)out_size;
}

// round 13
// speedup vs baseline: 1.8034x; 1.8034x over previous
#include <cuda_runtime.h>
#include <cuda_bf16.h>
#include <math.h>

// ============================================================================
// GAT: 2-layer graph attention, N=8192, F_in=29, F_hid=8, H=4, F_out=2
//
// exp-free O(N^2) attention:
//   w_ij = exp(LReLU(f1_i+f2_j) - C_i) = max(E1p_i*E2p_j, E1n_i*E2n_j)
// attn1: warp-level mma.sync.m16n8k8.tf32 — w generated in registers
// directly into A-fragments (f32x2 across head pairs; lo/hi halves feed
// head0/head1 frags for free); H from smem as B; den via constant ones
// column in a second n-tile. ~2.2x fewer warp-instructions than scalar.
// ============================================================================

#define N_NODES   8192
#define F_IN      29
#define F_HID     8
#define N_HEADS   4
#define GAT_ALPHA 0.2f

#define NCH1      16                     // attn1 j-chunks
#define JCH1      (N_NODES / NCH1)       // 512
#define NCH2      16                     // attn2 j-chunks
#define JCH2      (N_NODES / NCH2)       // 512

typedef unsigned long long ull;

// ---------------------------------------------------------------------------
// f32x2 helpers
// ---------------------------------------------------------------------------
__device__ __forceinline__ ull f2mul(ull a, ull b) {
    ull r; asm("mul.rn.f32x2 %0, %1, %2;" : "=l"(r) : "l"(a), "l"(b)); return r;
}
__device__ __forceinline__ ull f2add(ull a, ull b) {
    ull r; asm("add.rn.f32x2 %0, %1, %2;" : "=l"(r) : "l"(a), "l"(b)); return r;
}
__device__ __forceinline__ ull f2fma(ull a, ull b, ull c) {
    ull r; asm("fma.rn.f32x2 %0, %1, %2, %3;" : "=l"(r) : "l"(a), "l"(b), "l"(c)); return r;
}
__device__ __forceinline__ float2 f2lohi(ull v) {
    float2 r; asm("mov.b64 {%0, %1}, %2;" : "=f"(r.x), "=f"(r.y) : "l"(v)); return r;
}
__device__ __forceinline__ ull f2pack(float x, float y) {
    ull r; asm("mov.b64 %0, {%1, %2};" : "=l"(r) : "f"(x), "f"(y)); return r;
}
__device__ __forceinline__ unsigned lo32(ull v) { return (unsigned)v; }
__device__ __forceinline__ unsigned hi32(ull v) { return (unsigned)(v >> 32); }

// exact, order-independent float atomic max
__device__ __forceinline__ void atomicMaxF(float* addr, float v) {
    if (v >= 0.f) atomicMax((int*)addr, __float_as_int(v));
    else          atomicMin((unsigned int*)addr, __float_as_uint(v));
}

// m16n8k8 tf32 mma, fp32 accum (warp-level, register fragments)
__device__ __forceinline__ void mma_tf32(float c[4],
                                         unsigned a0, unsigned a1, unsigned a2, unsigned a3,
                                         unsigned b0, unsigned b1) {
    asm volatile(
        "mma.sync.aligned.m16n8k8.row.col.f32.tf32.tf32.f32 "
        "{%0,%1,%2,%3}, {%4,%5,%6,%7}, {%8,%9}, {%0,%1,%2,%3};"
        : "+f"(c[0]), "+f"(c[1]), "+f"(c[2]), "+f"(c[3])
        : "r"(a0), "r"(a1), "r"(a2), "r"(a3), "r"(b0), "r"(b1));
}

// ---------------------------------------------------------------------------
// Device scratch (static)
// ---------------------------------------------------------------------------
__device__ __align__(16) uint4 g_adjT4[(N_NODES / 128) * N_NODES];   // 8 MB [g128][i]
__device__ __align__(16) float g_E2[N_NODES * 8];       // [j][0..3]=hp0 (E2p01,E2n01) [4..7]=hp1
__device__ __align__(16) float g_HB[32 * N_NODES];      // [(h*8+k)][i] : feat k of head h
__device__ __align__(16) float g_row1[N_NODES * 8];     // [0..1]=e1p h01 [2..3]=e1n h01 [4..7]=h23
__device__ float g_f1_1[N_NODES * N_HEADS];
__device__ float g_f2_1[N_NODES * N_HEADS];
__device__ float g_m2[8];
__device__ float g_part1[NCH1 * N_NODES * 36];
__device__ __align__(16) float g_tile2F[4 * N_NODES];
__device__ float g_row2[N_NODES * 2];
__device__ float g_f1_2[N_NODES];
__device__ float g_f2_2[N_NODES];
__device__ float g_part2[NCH2 * N_NODES * 4];

// ---------------------------------------------------------------------------
// K0: pack adj into uint4 bitmasks (bit l of word c <-> j = 4l + c) + init m2
// ---------------------------------------------------------------------------
__global__ void gat_pack_adj(const int* __restrict__ adj) {
    if (blockIdx.x == 0 && threadIdx.x < 8)
        g_m2[threadIdx.x] = __int_as_float(0xff800000);
    int gw   = (blockIdx.x * blockDim.x + threadIdx.x) >> 5;
    int lane = threadIdx.x & 31;
    int i = gw & (N_NODES - 1);
    int g = gw >> 13;
    const int4* p = (const int4*)(adj + (size_t)i * N_NODES + g * 128);
    int4 v = p[lane];
    unsigned m0 = __ballot_sync(0xFFFFFFFFu, v.x > 0);
    unsigned m1 = __ballot_sync(0xFFFFFFFFu, v.y > 0);
    unsigned m2 = __ballot_sync(0xFFFFFFFFu, v.z > 0);
    unsigned m3 = __ballot_sync(0xFFFFFFFFu, v.w > 0);
    if (lane == 0) g_adjT4[g * N_NODES + i] = make_uint4(m0, m1, m2, m3);
}

// ---------------------------------------------------------------------------
// K1: h = x@W per head, f1/f2, fused per-head max(f2); h -> g_HB layout
// ---------------------------------------------------------------------------
__global__ void gat_prep1(const float* __restrict__ x,
                          const float* __restrict__ Wh,
                          const float* __restrict__ ah) {
    __shared__ float sW[N_HEADS * F_IN * F_HID];
    __shared__ float sa[N_HEADS * 2 * F_HID];
    for (int q = threadIdx.x; q < N_HEADS * F_IN * F_HID; q += blockDim.x) sW[q] = Wh[q];
    if (threadIdx.x < 64) sa[threadIdx.x] = ah[threadIdx.x];
    __syncthreads();

    int i = blockIdx.x * blockDim.x + threadIdx.x;
    int lane = threadIdx.x & 31;
    float xr[F_IN];
#pragma unroll
    for (int c = 0; c < F_IN; c++) xr[c] = x[i * F_IN + c];

#pragma unroll
    for (int h = 0; h < N_HEADS; h++) {
        float hv[F_HID];
#pragma unroll
        for (int k = 0; k < F_HID; k++) hv[k] = 0.f;
#pragma unroll
        for (int c = 0; c < F_IN; c++) {
            float xc = xr[c];
#pragma unroll
            for (int k = 0; k < F_HID; k++)
                hv[k] = fmaf(xc, sW[h * (F_IN * F_HID) + c * F_HID + k], hv[k]);
        }
        float f1 = 0.f, f2 = 0.f;
#pragma unroll
        for (int k = 0; k < F_HID; k++) {
            f1 = fmaf(hv[k], sa[h * 16 + k], f1);
            f2 = fmaf(hv[k], sa[h * 16 + 8 + k], f2);
        }
#pragma unroll
        for (int k = 0; k < F_HID; k++)
            g_HB[(size_t)(h * 8 + k) * N_NODES + i] = hv[k];
        g_f1_1[i * N_HEADS + h] = f1;
        g_f2_1[i * N_HEADS + h] = f2;
        float m = f2;
#pragma unroll
        for (int s = 16; s > 0; s >>= 1) m = fmaxf(m, __shfl_xor_sync(0xFFFFFFFFu, m, s));
        if (lane == 0) atomicMaxF(&g_m2[h], m);
    }
}

// ---------------------------------------------------------------------------
// K2: layer-1 E1/E2 factors
// ---------------------------------------------------------------------------
__global__ void gat_prep1b() {
    int i = blockIdx.x * blockDim.x + threadIdx.x;
#pragma unroll
    for (int h = 0; h < N_HEADS; h++) {
        int gp = h >> 1, o = h & 1;
        float m2 = g_m2[h];
        float t  = g_f1_1[i * N_HEADS + h] + m2;
        float C  = fmaxf(t, GAT_ALPHA * t);
        g_row1[i * 8 + gp * 4 + o]     = expf(t - C);
        g_row1[i * 8 + gp * 4 + 2 + o] = expf(GAT_ALPHA * t - C);
        float u = g_f2_1[i * N_HEADS + h] - m2;
        g_E2[i * 8 + gp * 4 + o]     = expf(u);
        g_E2[i * 8 + gp * 4 + 2 + o] = expf(GAT_ALPHA * u);
    }
}

// w-gen for one (row, j) position, one head pair: returns packed (w_h0, w_h1)
__device__ __forceinline__ ull wgen(ull e1p, ull e1n, ull E2p, ull E2n, bool b) {
    ull wp = f2mul(e1p, E2p);
    ull wn = f2mul(e1n, E2n);
    float2 p = f2lohi(wp), n = f2lohi(wn);
    float w0 = b ? fmaxf(p.x, n.x) : 0.f;
    float w1 = b ? fmaxf(p.y, n.y) : 0.f;
    return f2pack(w0, w1);
}

// ---------------------------------------------------------------------------
// K3: layer-1 attention via m16n8k8 tf32 MMA.
// CTA 256 thr = 8 warps; warp = one 16-row m-tile (CTA covers 128 rows).
// Grid (64, NCH1). j-chunk 512 = 4 tiles of 128; k-loop 16 per tile.
// ---------------------------------------------------------------------------
__global__ void __launch_bounds__(256, 2) gat_attn1() {
    __shared__ __align__(16) float sE2[128][8];       // 4 KB
    __shared__ __align__(16) float sHB[4][8][132];    // 16.9 KB (pad 132: conflict-free)

    const int tid  = threadIdx.x;
    const int wid  = tid >> 5;
    const int lane = tid & 31;
    const int g    = lane >> 2;      // groupID (0..7)
    const int tig  = lane & 3;       // thread-in-group

    const int chunk = blockIdx.y;
    const int row0 = blockIdx.x * 128 + wid * 16 + g;
    const int row8 = row0 + 8;

    // e1 factors, fixed for this warp's rows (16 regs)
    ulonglong2 e1A0 = *(const ulonglong2*)(g_row1 + (size_t)row0 * 8);      // hp0: e1p01,e1n01
    ulonglong2 e1B0 = *(const ulonglong2*)(g_row1 + (size_t)row0 * 8 + 4);  // hp1
    ulonglong2 e1A8 = *(const ulonglong2*)(g_row1 + (size_t)row8 * 8);
    ulonglong2 e1B8 = *(const ulonglong2*)(g_row1 + (size_t)row8 * 8 + 4);

    // constant ones-column B for the den n-tile (col 0)
    const unsigned bden = (g == 0) ? __float_as_uint(1.0f) : 0u;

    float c[4][2][4];   // [head][ntile: 0=feats,1=den][frag]
#pragma unroll
    for (int h = 0; h < 4; h++)
#pragma unroll
        for (int n = 0; n < 2; n++)
#pragma unroll
            for (int q = 0; q < 4; q++) c[h][n][q] = 0.f;

    const unsigned* adjw = (const unsigned*)g_adjT4;

    for (int jt = 0; jt < JCH1; jt += 128) {
        const int jb = chunk * JCH1 + jt;
        __syncthreads();
        // fill sE2: 1024 floats = 256 float4
        {
            const float4* s = (const float4*)(g_E2 + (size_t)jb * 8);
            ((float4*)sE2)[tid] = s[tid];
        }
        // fill sHB: 32 rows x 128 floats; thread: row tid/8, 16 floats
        {
            int r = tid >> 3, q = tid & 7;
            const float4* s = (const float4*)(g_HB + (size_t)r * N_NODES + jb);
            float* d = &sHB[0][0][0] + r * 132 + q * 16;
#pragma unroll
            for (int v = 0; v < 4; v++) ((float4*)d)[v] = s[q * 4 + v];
        }
        __syncthreads();

        // adjacency words: word 'tig' covers bits l: j_local = 4l + tig
        unsigned mlo = adjw[((size_t)(jb >> 7) * N_NODES + row0) * 4 + tig];
        unsigned mhi = adjw[((size_t)(jb >> 7) * N_NODES + row8) * 4 + tig];

#pragma unroll 4
        for (int k = 0; k < 16; k++) {
            const int j0 = k * 8 + tig;          // A col tig / B row tig
            const int j1 = j0 + 4;               // A col tig+4 / B row tig+4

            ulonglong2 E2a = *(const ulonglong2*)(&sE2[j0][0]);   // hp0 (E2p01,E2n01)
            ulonglong2 E2b = *(const ulonglong2*)(&sE2[j0][4]);   // hp1
            ulonglong2 F2a = *(const ulonglong2*)(&sE2[j1][0]);
            ulonglong2 F2b = *(const ulonglong2*)(&sE2[j1][4]);

            bool b00 = (mlo >> (2 * k)) & 1u;       // (row0, j0)
            bool b01 = (mlo >> (2 * k + 1)) & 1u;   // (row0, j1)
            bool b10 = (mhi >> (2 * k)) & 1u;       // (row8, j0)
            bool b11 = (mhi >> (2 * k + 1)) & 1u;   // (row8, j1)

            // A fragments: a0=(g,j0) a1=(g+8,j0) a2=(g,j1) a3=(g+8,j1)
            ull wA0 = wgen(e1A0.x, e1A0.y, E2a.x, E2a.y, b00);   // hp0
            ull wA1 = wgen(e1A8.x, e1A8.y, E2a.x, E2a.y, b10);
            ull wA2 = wgen(e1A0.x, e1A0.y, F2a.x, F2a.y, b01);
            ull wA3 = wgen(e1A8.x, e1A8.y, F2a.x, F2a.y, b11);
            ull wB0 = wgen(e1B0.x, e1B0.y, E2b.x, E2b.y, b00);   // hp1
            ull wB1 = wgen(e1B8.x, e1B8.y, E2b.x, E2b.y, b10);
            ull wB2 = wgen(e1B0.x, e1B0.y, F2b.x, F2b.y, b01);
            ull wB3 = wgen(e1B8.x, e1B8.y, F2b.x, F2b.y, b11);

#pragma unroll
            for (int h = 0; h < 4; h++) {
                // B fragment: b0 = H[j0][feat g], b1 = H[j1][feat g] of head h
                unsigned b0 = __float_as_uint(sHB[h][g][j0]);
                unsigned b1 = __float_as_uint(sHB[h][g][j1]);
                unsigned a0, a1, a2, a3;
                if (h == 0)      { a0 = lo32(wA0); a1 = lo32(wA1); a2 = lo32(wA2); a3 = lo32(wA3); }
                else if (h == 1) { a0 = hi32(wA0); a1 = hi32(wA1); a2 = hi32(wA2); a3 = hi32(wA3); }
                else if (h == 2) { a0 = lo32(wB0); a1 = lo32(wB1); a2 = lo32(wB2); a3 = lo32(wB3); }
                else             { a0 = hi32(wB0); a1 = hi32(wB1); a2 = hi32(wB2); a3 = hi32(wB3); }
                mma_tf32(c[h][0], a0, a1, a2, a3, b0, b1);
                mma_tf32(c[h][1], a0, a1, a2, a3, bden, bden);
            }
        }
    }

    // epilogue: c-frag cols = 2*tig, 2*tig+1 (feats); den = ntile1 col 0 (tig==0)
    float* p0 = g_part1 + ((size_t)chunk * N_NODES + row0) * 36;
    float* p8 = g_part1 + ((size_t)chunk * N_NODES + row8) * 36;
#pragma unroll
    for (int h = 0; h < 4; h++) {
        p0[h * 9 + 2 * tig]     = c[h][0][0];
        p0[h * 9 + 2 * tig + 1] = c[h][0][1];
        p8[h * 9 + 2 * tig]     = c[h][0][2];
        p8[h * 9 + 2 * tig + 1] = c[h][0][3];
        if (tig == 0) {
            p0[h * 9 + 8] = c[h][1][0];
            p8[h * 9 + 8] = c[h][1][2];
        }
    }
}

// ---------------------------------------------------------------------------
// K4: combine layer-1 partials, ELU, layer-2 h/f1/f2, fused max(f2_2)
// ---------------------------------------------------------------------------
__global__ void gat_comb1(const float* __restrict__ Wout,
                          const float* __restrict__ aout) {
    int i = blockIdx.x * blockDim.x + threadIdx.x;
    int lane = threadIdx.x & 31;
    float den[N_HEADS];
    float acc[N_HEADS][F_HID];
#pragma unroll
    for (int h = 0; h < N_HEADS; h++) {
        den[h] = 0.f;
#pragma unroll
        for (int k = 0; k < F_HID; k++) acc[h][k] = 0.f;
    }
    for (int c = 0; c < NCH1; c++) {
        const float* p = g_part1 + ((size_t)c * N_NODES + i) * 36;
#pragma unroll
        for (int h = 0; h < N_HEADS; h++) {
#pragma unroll
            for (int k = 0; k < F_HID; k++) acc[h][k] += p[h * 9 + k];
            den[h] += p[h * 9 + 8];
        }
    }
    float hc[N_HEADS * F_HID];
#pragma unroll
    for (int h = 0; h < N_HEADS; h++) {
        float inv = 1.0f / den[h];
#pragma unroll
        for (int k = 0; k < F_HID; k++) {
            float o = acc[h][k] * inv;
            hc[h * 8 + k] = (o > 0.f) ? o : expm1f(o);
        }
    }
    float h2_0 = 0.f, h2_1 = 0.f;
#pragma unroll
    for (int q = 0; q < 32; q++) {
        h2_0 = fmaf(hc[q], __ldg(&Wout[q * 2 + 0]), h2_0);
        h2_1 = fmaf(hc[q], __ldg(&Wout[q * 2 + 1]), h2_1);
    }
    float a0 = __ldg(&aout[0]), a1 = __ldg(&aout[1]);
    float a2 = __ldg(&aout[2]), a3 = __ldg(&aout[3]);
    g_tile2F[2 * N_NODES + i] = h2_0;
    g_tile2F[3 * N_NODES + i] = h2_1;
    g_f1_2[i] = h2_0 * a0 + h2_1 * a1;
    float f2 = h2_0 * a2 + h2_1 * a3;
    g_f2_2[i] = f2;
    float m = f2;
#pragma unroll
    for (int s = 16; s > 0; s >>= 1) m = fmaxf(m, __shfl_xor_sync(0xFFFFFFFFu, m, s));
    if (lane == 0) atomicMaxF(&g_m2[4], m);
}

// ---------------------------------------------------------------------------
// K5: layer-2 E1/E2
// ---------------------------------------------------------------------------
__global__ void gat_prep2() {
    int i = blockIdx.x * blockDim.x + threadIdx.x;
    float m2 = g_m2[4];
    float t = g_f1_2[i] + m2;
    float C = fmaxf(t, GAT_ALPHA * t);
    g_row2[i * 2]     = expf(t - C);
    g_row2[i * 2 + 1] = expf(GAT_ALPHA * t - C);
    float u = g_f2_2[i] - m2;
    g_tile2F[0 * N_NODES + i] = expf(u);
    g_tile2F[1 * N_NODES + i] = expf(GAT_ALPHA * u);
}

// ---------------------------------------------------------------------------
// K6: layer-2 attention (R9 config — proven). 2 rows/thread, chunk 512.
// ---------------------------------------------------------------------------
__global__ void __launch_bounds__(128, 6) gat_attn2() {
    __shared__ __align__(16) float tE[4][JCH2];   // 8 KB
    int t = threadIdx.x;
    int i0 = blockIdx.x * 256 + t;
    int i1 = i0 + 128;
    int jbase = blockIdx.y * JCH2;

#pragma unroll
    for (int f = 0; f < 4; f++) {
        const float4* src = (const float4*)(g_tile2F + (size_t)f * N_NODES + jbase);
        float4* dst = (float4*)tE[f];
        dst[t] = src[t];
    }
    __syncthreads();

    ull e1p0 = f2pack(g_row2[i0 * 2], g_row2[i0 * 2]);
    ull e1n0 = f2pack(g_row2[i0 * 2 + 1], g_row2[i0 * 2 + 1]);
    ull e1p1 = f2pack(g_row2[i1 * 2], g_row2[i1 * 2]);
    ull e1n1 = f2pack(g_row2[i1 * 2 + 1], g_row2[i1 * 2 + 1]);

    ull den0 = 0, a00 = 0, a10 = 0;
    ull den1 = 0, a01 = 0, a11 = 0;

    for (int jt = 0; jt < JCH2; jt += 128) {
        int g = (jbase + jt) >> 7;
        uint4 B0 = g_adjT4[(size_t)g * N_NODES + i0];
        uint4 B1 = g_adjT4[(size_t)g * N_NODES + i1];
        unsigned mw0[4] = {B0.x, B0.y, B0.z, B0.w};
        unsigned mw1[4] = {B1.x, B1.y, B1.z, B1.w};

#pragma unroll
        for (int cc = 0; cc < 4; cc += 2) {
            unsigned m0a = mw0[cc], m0b = mw0[cc + 1];
            unsigned m1a = mw1[cc], m1b = mw1[cc + 1];
#pragma unroll 8
            for (int l = 0; l < 32; l++) {
                int jloc = jt + 4 * l + cc;
                ull E2p2 = *(const ull*)(&tE[0][jloc]);
                ull E2n2 = *(const ull*)(&tE[1][jloc]);
                ull H02  = *(const ull*)(&tE[2][jloc]);
                ull H12  = *(const ull*)(&tE[3][jloc]);
                bool a0a = (m0a >> l) & 1u, a0b = (m0b >> l) & 1u;
                bool a1a = (m1a >> l) & 1u, a1b = (m1b >> l) & 1u;

                ull wp0 = f2mul(e1p0, E2p2), wn0 = f2mul(e1n0, E2n2);
                ull wp1 = f2mul(e1p1, E2p2), wn1 = f2mul(e1n1, E2n2);
                float2 p0 = f2lohi(wp0), n0 = f2lohi(wn0);
                float2 p1 = f2lohi(wp1), n1 = f2lohi(wn1);
                float w00 = a0a ? fmaxf(p0.x, n0.x) : 0.f;
                float w01 = a0b ? fmaxf(p0.y, n0.y) : 0.f;
                float w10 = a1a ? fmaxf(p1.x, n1.x) : 0.f;
                float w11 = a1b ? fmaxf(p1.y, n1.y) : 0.f;
                ull w0 = f2pack(w00, w01), w1 = f2pack(w10, w11);
                den0 = f2add(den0, w0);
                a00 = f2fma(w0, H02, a00);
                a10 = f2fma(w0, H12, a10);
                den1 = f2add(den1, w1);
                a01 = f2fma(w1, H02, a01);
                a11 = f2fma(w1, H12, a11);
            }
        }
    }

    {
        float2 d = f2lohi(den0), x0 = f2lohi(a00), x1 = f2lohi(a10);
        float* p = g_part2 + ((size_t)blockIdx.y * N_NODES + i0) * 4;
        p[0] = d.x + d.y; p[1] = x0.x + x0.y; p[2] = x1.x + x1.y;
    }
    {
        float2 d = f2lohi(den1), x0 = f2lohi(a01), x1 = f2lohi(a11);
        float* p = g_part2 + ((size_t)blockIdx.y * N_NODES + i1) * 4;
        p[0] = d.x + d.y; p[1] = x0.x + x0.y; p[2] = x1.x + x1.y;
    }
}

// ---------------------------------------------------------------------------
// K7: combine, ELU, log_softmax
// ---------------------------------------------------------------------------
__global__ void gat_final(float* __restrict__ out) {
    int i = blockIdx.x * blockDim.x + threadIdx.x;
    float den = 0.f, a0 = 0.f, a1 = 0.f;
    for (int c = 0; c < NCH2; c++) {
        const float* p = g_part2 + ((size_t)c * N_NODES + i) * 4;
        den += p[0]; a0 += p[1]; a1 += p[2];
    }
    float inv = 1.0f / den;
    float o0 = a0 * inv; o0 = (o0 > 0.f) ? o0 : expm1f(o0);
    float o1 = a1 * inv; o1 = (o1 > 0.f) ? o1 : expm1f(o1);
    float m = fmaxf(o0, o1);
    float l = logf(expf(o0 - m) + expf(o1 - m)) + m;
    out[i * 2]     = o0 - l;
    out[i * 2 + 1] = o1 - l;
}

// ---------------------------------------------------------------------------
// launch (attn1 is launch #4 for the ncu window)
// ---------------------------------------------------------------------------
extern "C" void kernel_launch(void* const* d_in, const int* in_sizes, int n_in,
                              void* d_out, int out_size) {
    const float* x  = nullptr;
    const int*   adj = nullptr;
    const float* Wh = nullptr;
    const float* ah = nullptr;
    const float* Wo = nullptr;
    const float* ao = nullptr;
    int found64 = 0;
    for (int k = 0; k < n_in; k++) {
        long s = in_sizes[k];
        if (s == (long)N_NODES * F_IN)          x   = (const float*)d_in[k];
        else if (s == (long)N_NODES * N_NODES)  adj = (const int*)d_in[k];
        else if (s == N_HEADS * F_IN * F_HID)   Wh  = (const float*)d_in[k];
        else if (s == 64) { if (found64++ == 0) ah = (const float*)d_in[k]; else Wo = (const float*)d_in[k]; }
        else if (s == 4)                        ao  = (const float*)d_in[k];
    }

    gat_pack_adj<<<65536, 256>>>(adj);
    gat_prep1<<<N_NODES / 128, 128>>>(x, Wh, ah);
    gat_prep1b<<<N_NODES / 128, 128>>>();
    gat_attn1<<<dim3(N_NODES / 128, NCH1), 256>>>();
    gat_comb1<<<N_NODES / 128, 128>>>(Wo, ao);
    gat_prep2<<<N_NODES / 128, 128>>>();
    gat_attn2<<<dim3(N_NODES / 256, NCH2), 128>>>();
    gat_final<<<N_NODES / 128, 128>>>((float*)d_out);
    (void)out_size;
}